// round 4
// baseline (speedup 1.0000x reference)
#include <cuda_runtime.h>

#define B_ 4
#define L_ 512
#define D_ 256

__device__ __forceinline__ float tanh_fast(float x) {
    float y;
    asm("tanh.approx.f32 %0, %1;" : "=f"(y) : "f"(x));
    return y;
}

// ---------------------------------------------------------------------------
// Kernel A: symmetric pairwise tanh scores.
// Grid (136, B): 136 = upper-triangular 32x32 tile pairs of a 512x512 matrix.
// Block 256 threads. Writes scores into the alpha slice of d_out (scratch).
// ---------------------------------------------------------------------------
__global__ __launch_bounds__(256) void scores_kernel(
    const float* __restrict__ H, const float* __restrict__ w,
    float* __restrict__ scores)
{
    extern __shared__ float sm[];
    float* s_hi  = sm;                  // [32][256] row-major
    float* s_hjT = s_hi + 32 * D_;      // [256][33] transposed, padded
    float* s_w   = s_hjT + D_ * 33;     // [256]
    float* s_tr  = s_w + D_;            // [32][33] transpose staging

    int p  = blockIdx.x;
    int b  = blockIdx.y;
    int ti = 0;
    while (p >= 16 - ti) { p -= 16 - ti; ti++; }
    int tj = ti + p;
    int i0 = ti * 32, j0 = tj * 32;

    int tid  = threadIdx.x;
    int warp = tid >> 5, lane = tid & 31;
    const float* Hb = H + (size_t)b * L_ * D_;

    // weights
    if (tid < 64) ((float4*)s_w)[tid] = ((const float4*)w)[tid];

    // Hi tile row-major (broadcast consumer)
    {
        const float4* src = (const float4*)(Hb + (size_t)i0 * D_);
        float4* dst = (float4*)s_hi;
        #pragma unroll
        for (int k = 0; k < 8; k++) dst[tid + 256 * k] = src[tid + 256 * k];
    }
    // Hj tile transposed [d][j], stride 33, conflict-free staging:
    // each warp: 4 j-rows; lane -> (row = lane>>3, d-subblock = lane&7)
    {
        int jr = warp * 4 + (lane >> 3);
        int m4 = lane & 7;
        const float* src = Hb + (size_t)(j0 + jr) * D_;
        #pragma unroll
        for (int it = 0; it < 8; it++) {
            int d = it * 32 + m4 * 4;
            float4 v = *(const float4*)(src + d);
            s_hjT[(d + 0) * 33 + jr] = v.x;
            s_hjT[(d + 1) * 33 + jr] = v.y;
            s_hjT[(d + 2) * 33 + jr] = v.z;
            s_hjT[(d + 3) * 33 + jr] = v.w;
        }
    }
    __syncthreads();

    // compute: warp handles 4 i-rows, lane -> j
    float acc[4] = {0.f, 0.f, 0.f, 0.f};
    int ib = warp * 4;
    const float* hi0 = s_hi + (size_t)(ib + 0) * D_;
    const float* hi1 = s_hi + (size_t)(ib + 1) * D_;
    const float* hi2 = s_hi + (size_t)(ib + 2) * D_;
    const float* hi3 = s_hi + (size_t)(ib + 3) * D_;

    #pragma unroll 2
    for (int d = 0; d < D_; d += 4) {
        float wv[4], a0[4], a1[4], a2[4], a3[4];
        *(float4*)wv = *(const float4*)(s_w + d);
        *(float4*)a0 = *(const float4*)(hi0 + d);
        *(float4*)a1 = *(const float4*)(hi1 + d);
        *(float4*)a2 = *(const float4*)(hi2 + d);
        *(float4*)a3 = *(const float4*)(hi3 + d);
        #pragma unroll
        for (int k = 0; k < 4; k++) {
            float hj = s_hjT[(d + k) * 33 + lane];
            acc[0] += tanh_fast(a0[k] + hj) * wv[k];
            acc[1] += tanh_fast(a1[k] + hj) * wv[k];
            acc[2] += tanh_fast(a2[k] + hj) * wv[k];
            acc[3] += tanh_fast(a3[k] + hj) * wv[k];
        }
    }

    float* Sb = scores + (size_t)b * L_ * L_;
    #pragma unroll
    for (int q = 0; q < 4; q++)
        Sb[(size_t)(i0 + ib + q) * L_ + j0 + lane] = acc[q];

    if (tj > ti) {
        // scatter transpose via smem (coalesced global stores)
        #pragma unroll
        for (int q = 0; q < 4; q++)
            s_tr[lane * 33 + ib + q] = acc[q];
        __syncthreads();
        int r0 = warp * 4;
        #pragma unroll
        for (int q = 0; q < 4; q++)
            Sb[(size_t)(j0 + r0 + q) * L_ + i0 + lane] = s_tr[(r0 + q) * 33 + lane];
    }
}

// ---------------------------------------------------------------------------
// Kernel B: softmax over j + r = alpha @ H.
// Grid (64, B): 8 i-rows per block. Block 256 threads.
// Reads scores from the alpha slice, overwrites with alpha, writes r.
// ---------------------------------------------------------------------------
__global__ __launch_bounds__(256) void softmax_r_kernel(
    const float* __restrict__ H,
    float* __restrict__ alpha,
    float* __restrict__ r)
{
    extern __shared__ float sm[];
    float* s_e  = sm;                 // [8][512] scores -> exp values
    float* s_hj = s_e + 8 * L_;       // [64][257] H tile, padded
    float* s_rs = s_hj + 64 * 257;    // [8] reciprocal sums

    int ib = blockIdx.x;
    int b  = blockIdx.y;
    int i0 = ib * 8;
    int tid = threadIdx.x, warp = tid >> 5, lane = tid & 31;
    const float* Hb = H + (size_t)b * L_ * D_;
    float* Ab = alpha + ((size_t)b * L_ + i0) * L_;

    // load 8x512 scores (contiguous)
    {
        const float4* src = (const float4*)Ab;
        float4* dst = (float4*)s_e;
        #pragma unroll
        for (int k = 0; k < 4; k++) dst[tid + 256 * k] = src[tid + 256 * k];
    }
    __syncthreads();

    // softmax: one warp per row
    {
        float* row = s_e + (size_t)warp * L_;
        float v[16];
        float m = -1e30f;
        #pragma unroll
        for (int k = 0; k < 16; k++) { v[k] = row[lane + 32 * k]; m = fmaxf(m, v[k]); }
        #pragma unroll
        for (int o = 16; o > 0; o >>= 1) m = fmaxf(m, __shfl_xor_sync(0xffffffffu, m, o));
        float s = 0.f;
        #pragma unroll
        for (int k = 0; k < 16; k++) { v[k] = __expf(v[k] - m); s += v[k]; row[lane + 32 * k] = v[k]; }
        #pragma unroll
        for (int o = 16; o > 0; o >>= 1) s += __shfl_xor_sync(0xffffffffu, s, o);
        float rs = 1.f / s;
        if (lane == 0) s_rs[warp] = rs;
        float* arow = Ab + (size_t)warp * L_;
        #pragma unroll
        for (int k = 0; k < 16; k++) arow[lane + 32 * k] = v[k] * rs;
    }
    __syncthreads();

    // r[i][d] = rs[i] * sum_j e[i][j] * H[j][d]; thread owns d = tid, 8 i accumulators
    float acc[8] = {0.f, 0.f, 0.f, 0.f, 0.f, 0.f, 0.f, 0.f};
    for (int jt = 0; jt < 8; jt++) {
        // stage 64 H rows, conflict-free
        #pragma unroll
        for (int g = 0; g < 2; g++) {
            int jr = warp * 8 + g * 4 + (lane >> 3);
            int m4 = lane & 7;
            const float* src = Hb + (size_t)(jt * 64 + jr) * D_;
            #pragma unroll
            for (int it = 0; it < 8; it++) {
                int d = it * 32 + m4 * 4;
                float4 v = *(const float4*)(src + d);
                float* dstp = s_hj + (size_t)jr * 257 + d;
                dstp[0] = v.x; dstp[1] = v.y; dstp[2] = v.z; dstp[3] = v.w;
            }
        }
        __syncthreads();

        int jb = jt * 64;
        for (int j = 0; j < 64; j += 4) {
            float a[8][4];
            #pragma unroll
            for (int i = 0; i < 8; i++)
                *(float4*)a[i] = *(const float4*)(s_e + (size_t)i * L_ + jb + j);
            #pragma unroll
            for (int jj = 0; jj < 4; jj++) {
                float hv = s_hj[(size_t)(j + jj) * 257 + tid];
                #pragma unroll
                for (int i = 0; i < 8; i++) acc[i] += a[i][jj] * hv;
            }
        }
        __syncthreads();
    }

    float* rb = r + ((size_t)b * L_ + i0) * D_;
    #pragma unroll
    for (int i = 0; i < 8; i++)
        rb[(size_t)i * D_ + tid] = acc[i] * s_rs[i];
}

// ---------------------------------------------------------------------------
extern "C" void kernel_launch(void* const* d_in, const int* in_sizes, int n_in,
                              void* d_out, int out_size)
{
    const float* H = (const float*)d_in[0];
    const float* w = (const float*)d_in[1];
    // d_in[2] = w_bias: softmax is shift-invariant and scores are not an
    // output, so the bias has no effect on (r, alpha) -> intentionally unused.

    float* out   = (float*)d_out;
    float* r     = out;                          // (B, L, D)
    float* alpha = out + (size_t)B_ * L_ * D_;   // (B, L, L); also scores scratch

    size_t smA = (size_t)(32 * D_ + D_ * 33 + D_ + 32 * 33) * sizeof(float);
    size_t smB = (size_t)(8 * L_ + 64 * 257 + 8) * sizeof(float);
    cudaFuncSetAttribute(scores_kernel,   cudaFuncAttributeMaxDynamicSharedMemorySize, (int)smA);
    cudaFuncSetAttribute(softmax_r_kernel, cudaFuncAttributeMaxDynamicSharedMemorySize, (int)smB);

    scores_kernel<<<dim3(136, B_), 256, smA>>>(H, w, alpha);
    softmax_r_kernel<<<dim3(64, B_), 256, smB>>>(H, alpha, r);
}

// round 6
// speedup vs baseline: 1.0004x; 1.0004x over previous
#include <cuda_runtime.h>

#define B_ 4
#define L_ 512
#define D_ 256

__device__ __forceinline__ float tanh_fast(float x) {
    float y;
    asm("tanh.approx.f32 %0, %1;" : "=f"(y) : "f"(x));
    return y;
}

// ---------------------------------------------------------------------------
// Kernel A: symmetric pairwise tanh scores. (unchanged — at MUFU roofline)
// Grid (136, B): 136 = upper-triangular 32x32 tile pairs of a 512x512 matrix.
// Block 256 threads. Writes scores into the alpha slice of d_out (scratch).
// ---------------------------------------------------------------------------
__global__ __launch_bounds__(256) void scores_kernel(
    const float* __restrict__ H, const float* __restrict__ w,
    float* __restrict__ scores)
{
    extern __shared__ float sm[];
    float* s_hi  = sm;                  // [32][256] row-major
    float* s_hjT = s_hi + 32 * D_;      // [256][33] transposed, padded
    float* s_w   = s_hjT + D_ * 33;     // [256]
    float* s_tr  = s_w + D_;            // [32][33] transpose staging

    int p  = blockIdx.x;
    int b  = blockIdx.y;
    int ti = 0;
    while (p >= 16 - ti) { p -= 16 - ti; ti++; }
    int tj = ti + p;
    int i0 = ti * 32, j0 = tj * 32;

    int tid  = threadIdx.x;
    int warp = tid >> 5, lane = tid & 31;
    const float* Hb = H + (size_t)b * L_ * D_;

    if (tid < 64) ((float4*)s_w)[tid] = ((const float4*)w)[tid];

    {
        const float4* src = (const float4*)(Hb + (size_t)i0 * D_);
        float4* dst = (float4*)s_hi;
        #pragma unroll
        for (int k = 0; k < 8; k++) dst[tid + 256 * k] = src[tid + 256 * k];
    }
    {
        int jr = warp * 4 + (lane >> 3);
        int m4 = lane & 7;
        const float* src = Hb + (size_t)(j0 + jr) * D_;
        #pragma unroll
        for (int it = 0; it < 8; it++) {
            int d = it * 32 + m4 * 4;
            float4 v = *(const float4*)(src + d);
            s_hjT[(d + 0) * 33 + jr] = v.x;
            s_hjT[(d + 1) * 33 + jr] = v.y;
            s_hjT[(d + 2) * 33 + jr] = v.z;
            s_hjT[(d + 3) * 33 + jr] = v.w;
        }
    }
    __syncthreads();

    float acc[4] = {0.f, 0.f, 0.f, 0.f};
    int ib = warp * 4;
    const float* hi0 = s_hi + (size_t)(ib + 0) * D_;
    const float* hi1 = s_hi + (size_t)(ib + 1) * D_;
    const float* hi2 = s_hi + (size_t)(ib + 2) * D_;
    const float* hi3 = s_hi + (size_t)(ib + 3) * D_;

    #pragma unroll 2
    for (int d = 0; d < D_; d += 4) {
        float wv[4], a0[4], a1[4], a2[4], a3[4];
        *(float4*)wv = *(const float4*)(s_w + d);
        *(float4*)a0 = *(const float4*)(hi0 + d);
        *(float4*)a1 = *(const float4*)(hi1 + d);
        *(float4*)a2 = *(const float4*)(hi2 + d);
        *(float4*)a3 = *(const float4*)(hi3 + d);
        #pragma unroll
        for (int k = 0; k < 4; k++) {
            float hj = s_hjT[(d + k) * 33 + lane];
            acc[0] += tanh_fast(a0[k] + hj) * wv[k];
            acc[1] += tanh_fast(a1[k] + hj) * wv[k];
            acc[2] += tanh_fast(a2[k] + hj) * wv[k];
            acc[3] += tanh_fast(a3[k] + hj) * wv[k];
        }
    }

    float* Sb = scores + (size_t)b * L_ * L_;
    #pragma unroll
    for (int q = 0; q < 4; q++)
        Sb[(size_t)(i0 + ib + q) * L_ + j0 + lane] = acc[q];

    if (tj > ti) {
        #pragma unroll
        for (int q = 0; q < 4; q++)
            s_tr[lane * 33 + ib + q] = acc[q];
        __syncthreads();
        int r0 = warp * 4;
        #pragma unroll
        for (int q = 0; q < 4; q++)
            Sb[(size_t)(j0 + r0 + q) * L_ + i0 + lane] = s_tr[(r0 + q) * 33 + lane];
    }
}

// ---------------------------------------------------------------------------
// Kernel B v2: softmax over j + r = alpha @ H.
// Grid (64, B), 512 threads (16 warps). 8 i-rows per block.
// j-loop split across warp halves: each super-step stages 64 H rows; warps
// 0-7 contract rows [0,32), warps 8-15 rows [32,64). Partial accumulators
// merged through smem. Doubles warps/SM (13.8 -> 27.7) at constant H traffic.
// ---------------------------------------------------------------------------
__global__ __launch_bounds__(512, 2) void softmax_r_kernel(
    const float* __restrict__ H,
    float* __restrict__ alpha,
    float* __restrict__ r)
{
    extern __shared__ float sm[];
    float* s_e   = sm;                  // [8][512] scores -> softmax'd probs
    float* s_hj  = s_e + 8 * L_;        // [64][257] H super-tile, padded
    float* s_red = s_hj + 64 * 257;     // [8][256] partial-acc reduction
    float* s_rs  = s_red + 8 * 256;     // [8] reciprocal sums

    int ib = blockIdx.x;
    int b  = blockIdx.y;
    int i0 = ib * 8;
    int tid = threadIdx.x, warp = tid >> 5, lane = tid & 31;
    int half = tid >> 8;                // 0: warps 0-7, 1: warps 8-15
    int d    = tid & 255;
    const float* Hb = H + (size_t)b * L_ * D_;
    float* Ab = alpha + ((size_t)b * L_ + i0) * L_;

    // load 8x512 scores (contiguous): 1024 float4 over 512 threads
    {
        const float4* src = (const float4*)Ab;
        float4* dst = (float4*)s_e;
        #pragma unroll
        for (int k = 0; k < 2; k++) dst[tid + 512 * k] = src[tid + 512 * k];
    }
    __syncthreads();

    // softmax: one warp per row (warps 0-7)
    if (warp < 8) {
        float* row = s_e + (size_t)warp * L_;
        float v[16];
        float m = -1e30f;
        #pragma unroll
        for (int k = 0; k < 16; k++) { v[k] = row[lane + 32 * k]; m = fmaxf(m, v[k]); }
        #pragma unroll
        for (int o = 16; o > 0; o >>= 1) m = fmaxf(m, __shfl_xor_sync(0xffffffffu, m, o));
        float s = 0.f;
        #pragma unroll
        for (int k = 0; k < 16; k++) { v[k] = __expf(v[k] - m); s += v[k]; }
        #pragma unroll
        for (int o = 16; o > 0; o >>= 1) s += __shfl_xor_sync(0xffffffffu, s, o);
        float rs = 1.f / s;
        if (lane == 0) s_rs[warp] = rs;
        float* arow = Ab + (size_t)warp * L_;
        #pragma unroll
        for (int k = 0; k < 16; k++) {
            float a = v[k] * rs;
            row[lane + 32 * k]  = a;   // store normalized prob for the matmul
            arow[lane + 32 * k] = a;   // alpha output
        }
    }
    __syncthreads();

    // r[i][d] = sum_j alpha[i][j] * H[j][d]
    float acc[8] = {0.f, 0.f, 0.f, 0.f, 0.f, 0.f, 0.f, 0.f};
    for (int t = 0; t < 8; t++) {
        // stage 64 H rows (conflict-free): warp w -> rows w*4 + (lane>>3)
        {
            int jr = warp * 4 + (lane >> 3);
            int m4 = lane & 7;
            const float* src = Hb + (size_t)(t * 64 + jr) * D_;
            #pragma unroll
            for (int it = 0; it < 8; it++) {
                int dd = it * 32 + m4 * 4;
                float4 v = *(const float4*)(src + dd);
                float* dstp = s_hj + (size_t)jr * 257 + dd;
                dstp[0] = v.x; dstp[1] = v.y; dstp[2] = v.z; dstp[3] = v.w;
            }
        }
        __syncthreads();

        int jb = t * 64 + half * 32;          // global j base for this half
        const float* buf = s_hj + (size_t)half * 32 * 257;
        #pragma unroll 2
        for (int j = 0; j < 32; j += 4) {
            float a[8][4];
            #pragma unroll
            for (int i = 0; i < 8; i++)
                *(float4*)a[i] = *(const float4*)(s_e + (size_t)i * L_ + jb + j);
            #pragma unroll
            for (int jj = 0; jj < 4; jj++) {
                float hv = buf[(size_t)(j + jj) * 257 + d];
                #pragma unroll
                for (int i = 0; i < 8; i++) acc[i] += a[i][jj] * hv;
            }
        }
        __syncthreads();
    }

    // merge halves: half 1 publishes, half 0 adds and stores
    if (half == 1) {
        #pragma unroll
        for (int i = 0; i < 8; i++) s_red[i * 256 + d] = acc[i];
    }
    __syncthreads();
    if (half == 0) {
        float* rb = r + ((size_t)b * L_ + i0) * D_;
        #pragma unroll
        for (int i = 0; i < 8; i++)
            rb[(size_t)i * D_ + d] = acc[i] + s_red[i * 256 + d];
    }
}

// ---------------------------------------------------------------------------
extern "C" void kernel_launch(void* const* d_in, const int* in_sizes, int n_in,
                              void* d_out, int out_size)
{
    const float* H = (const float*)d_in[0];
    const float* w = (const float*)d_in[1];
    // d_in[2] = w_bias: softmax is shift-invariant and scores are not an
    // output, so the bias has no effect on (r, alpha) -> intentionally unused.

    float* out   = (float*)d_out;
    float* r     = out;                          // (B, L, D)
    float* alpha = out + (size_t)B_ * L_ * D_;   // (B, L, L); also scores scratch

    size_t smA = (size_t)(32 * D_ + D_ * 33 + D_ + 32 * 33) * sizeof(float);
    size_t smB = (size_t)(8 * L_ + 64 * 257 + 8 * 256 + 8) * sizeof(float);
    cudaFuncSetAttribute(scores_kernel,    cudaFuncAttributeMaxDynamicSharedMemorySize, (int)smA);
    cudaFuncSetAttribute(softmax_r_kernel, cudaFuncAttributeMaxDynamicSharedMemorySize, (int)smB);

    scores_kernel<<<dim3(136, B_), 256, smA>>>(H, w, alpha);
    softmax_r_kernel<<<dim3(64, B_), 512, smB>>>(H, alpha, r);
}

// round 16
// speedup vs baseline: 1.2547x; 1.2542x over previous
#include <cuda_runtime.h>

#define B_ 4
#define L_ 512
#define D_ 256

__device__ __forceinline__ float tanh_fast(float x) {
    float y;
    asm("tanh.approx.f32 %0, %1;" : "=f"(y) : "f"(x));
    return y;
}

// ---------------------------------------------------------------------------
// Kernel A: symmetric pairwise tanh scores. (unchanged — at MUFU roofline)
// ---------------------------------------------------------------------------
__global__ __launch_bounds__(256) void scores_kernel(
    const float* __restrict__ H, const float* __restrict__ w,
    float* __restrict__ scores)
{
    extern __shared__ float sm[];
    float* s_hi  = sm;                  // [32][256] row-major
    float* s_hjT = s_hi + 32 * D_;      // [256][33] transposed, padded
    float* s_w   = s_hjT + D_ * 33;     // [256]
    float* s_tr  = s_w + D_;            // [32][33] transpose staging

    int p  = blockIdx.x;
    int b  = blockIdx.y;
    int ti = 0;
    while (p >= 16 - ti) { p -= 16 - ti; ti++; }
    int tj = ti + p;
    int i0 = ti * 32, j0 = tj * 32;

    int tid  = threadIdx.x;
    int warp = tid >> 5, lane = tid & 31;
    const float* Hb = H + (size_t)b * L_ * D_;

    if (tid < 64) ((float4*)s_w)[tid] = ((const float4*)w)[tid];

    {
        const float4* src = (const float4*)(Hb + (size_t)i0 * D_);
        float4* dst = (float4*)s_hi;
        #pragma unroll
        for (int k = 0; k < 8; k++) dst[tid + 256 * k] = src[tid + 256 * k];
    }
    {
        int jr = warp * 4 + (lane >> 3);
        int m4 = lane & 7;
        const float* src = Hb + (size_t)(j0 + jr) * D_;
        #pragma unroll
        for (int it = 0; it < 8; it++) {
            int d = it * 32 + m4 * 4;
            float4 v = *(const float4*)(src + d);
            s_hjT[(d + 0) * 33 + jr] = v.x;
            s_hjT[(d + 1) * 33 + jr] = v.y;
            s_hjT[(d + 2) * 33 + jr] = v.z;
            s_hjT[(d + 3) * 33 + jr] = v.w;
        }
    }
    __syncthreads();

    float acc[4] = {0.f, 0.f, 0.f, 0.f};
    int ib = warp * 4;
    const float* hi0 = s_hi + (size_t)(ib + 0) * D_;
    const float* hi1 = s_hi + (size_t)(ib + 1) * D_;
    const float* hi2 = s_hi + (size_t)(ib + 2) * D_;
    const float* hi3 = s_hi + (size_t)(ib + 3) * D_;

    #pragma unroll 2
    for (int d = 0; d < D_; d += 4) {
        float wv[4], a0[4], a1[4], a2[4], a3[4];
        *(float4*)wv = *(const float4*)(s_w + d);
        *(float4*)a0 = *(const float4*)(hi0 + d);
        *(float4*)a1 = *(const float4*)(hi1 + d);
        *(float4*)a2 = *(const float4*)(hi2 + d);
        *(float4*)a3 = *(const float4*)(hi3 + d);
        #pragma unroll
        for (int k = 0; k < 4; k++) {
            float hj = s_hjT[(d + k) * 33 + lane];
            acc[0] += tanh_fast(a0[k] + hj) * wv[k];
            acc[1] += tanh_fast(a1[k] + hj) * wv[k];
            acc[2] += tanh_fast(a2[k] + hj) * wv[k];
            acc[3] += tanh_fast(a3[k] + hj) * wv[k];
        }
    }

    float* Sb = scores + (size_t)b * L_ * L_;
    #pragma unroll
    for (int q = 0; q < 4; q++)
        Sb[(size_t)(i0 + ib + q) * L_ + j0 + lane] = acc[q];

    if (tj > ti) {
        #pragma unroll
        for (int q = 0; q < 4; q++)
            s_tr[lane * 33 + ib + q] = acc[q];
        __syncthreads();
        int r0 = warp * 4;
        #pragma unroll
        for (int q = 0; q < 4; q++)
            Sb[(size_t)(j0 + r0 + q) * L_ + i0 + lane] = s_tr[(r0 + q) * 33 + lane];
    }
}

// ---------------------------------------------------------------------------
// Kernel B v3: softmax + r = alpha @ H, minimal shared-memory traffic.
// Grid (64, B), 256 threads. 8 i-rows per block.
// Softmax: warp w owns score row w entirely in registers (no smem roundtrip).
// Matmul: thread = (jg = tid>>6, dt = tid&63); owns d = dt*4..dt*4+3 (float4)
// and j-range [jg*128, jg*128+128). H read directly from L2 via LDG.128
// (one load feeds 8 i x 4 d = 32 FMAs); alpha read as warp-uniform broadcast
// LDS.128 (8 per 128 FMAs). No staging, no mainloop barriers.
// Partial accumulators of jg=1..3 merged through smem at the end.
// ---------------------------------------------------------------------------
__global__ __launch_bounds__(256, 3) void softmax_r_kernel(
    const float* __restrict__ H,
    float* __restrict__ alpha,
    float* __restrict__ r)
{
    __shared__ float s_e[8 * 512];       // softmax'd probs (16 KB)
    __shared__ float s_red[3 * 8 * 256]; // jg=1..3 partials (24 KB)

    int ibk = blockIdx.x;
    int b   = blockIdx.y;
    int i0  = ibk * 8;
    int tid = threadIdx.x, warp = tid >> 5, lane = tid & 31;
    int dt  = tid & 63;                  // d-group: owns floats dt*4..dt*4+3
    int jg  = tid >> 6;                  // j-group 0..3

    const float*  Hb = H + (size_t)b * L_ * D_;
    float*        Ab = alpha + ((size_t)b * L_ + i0) * L_;

    // ---- softmax: warp w handles score row w fully in registers ----
    {
        const float4* src = (const float4*)(Ab + (size_t)warp * L_);
        float4 v4[4];
        #pragma unroll
        for (int k = 0; k < 4; k++) v4[k] = src[lane + 32 * k];

        float* v = (float*)v4;
        float m = -1e30f;
        #pragma unroll
        for (int k = 0; k < 16; k++) m = fmaxf(m, v[k]);
        #pragma unroll
        for (int o = 16; o > 0; o >>= 1) m = fmaxf(m, __shfl_xor_sync(0xffffffffu, m, o));
        float s = 0.f;
        #pragma unroll
        for (int k = 0; k < 16; k++) { v[k] = __expf(v[k] - m); s += v[k]; }
        #pragma unroll
        for (int o = 16; o > 0; o >>= 1) s += __shfl_xor_sync(0xffffffffu, s, o);
        float rs = 1.f / s;
        #pragma unroll
        for (int k = 0; k < 16; k++) v[k] *= rs;

        float4* erow = (float4*)(s_e + (size_t)warp * L_);
        float4* arow = (float4*)(Ab + (size_t)warp * L_);
        #pragma unroll
        for (int k = 0; k < 4; k++) { erow[lane + 32 * k] = v4[k]; arow[lane + 32 * k] = v4[k]; }
    }
    __syncthreads();

    // ---- r partials: acc[i] is float4 over this thread's 4 d-values ----
    float4 acc[8];
    #pragma unroll
    for (int i = 0; i < 8; i++) acc[i] = make_float4(0.f, 0.f, 0.f, 0.f);

    const float4* Hv = (const float4*)Hb;    // index j*64 + dt
    int jbeg = jg * 128;
    #pragma unroll 1
    for (int j = jbeg; j < jbeg + 128; j += 4) {
        float4 hv0 = Hv[(size_t)(j + 0) * 64 + dt];
        float4 hv1 = Hv[(size_t)(j + 1) * 64 + dt];
        float4 hv2 = Hv[(size_t)(j + 2) * 64 + dt];
        float4 hv3 = Hv[(size_t)(j + 3) * 64 + dt];
        #pragma unroll
        for (int i = 0; i < 8; i++) {
            float4 a = *(const float4*)(s_e + (size_t)i * L_ + j);  // warp-uniform
            acc[i].x += a.x * hv0.x; acc[i].y += a.x * hv0.y;
            acc[i].z += a.x * hv0.z; acc[i].w += a.x * hv0.w;
            acc[i].x += a.y * hv1.x; acc[i].y += a.y * hv1.y;
            acc[i].z += a.y * hv1.z; acc[i].w += a.y * hv1.w;
            acc[i].x += a.z * hv2.x; acc[i].y += a.z * hv2.y;
            acc[i].z += a.z * hv2.z; acc[i].w += a.z * hv2.w;
            acc[i].x += a.w * hv3.x; acc[i].y += a.w * hv3.y;
            acc[i].z += a.w * hv3.z; acc[i].w += a.w * hv3.w;
        }
    }

    // ---- merge j-groups: jg 1..3 publish, jg 0 adds + stores ----
    if (jg > 0) {
        float4* dst = (float4*)(s_red + (size_t)(jg - 1) * 2048);
        #pragma unroll
        for (int i = 0; i < 8; i++) dst[i * 64 + dt] = acc[i];
    }
    __syncthreads();
    if (jg == 0) {
        float* rb = r + ((size_t)b * L_ + i0) * D_;
        #pragma unroll
        for (int i = 0; i < 8; i++) {
            float4 t = acc[i];
            #pragma unroll
            for (int g = 0; g < 3; g++) {
                float4 p = ((const float4*)(s_red + (size_t)g * 2048))[i * 64 + dt];
                t.x += p.x; t.y += p.y; t.z += p.z; t.w += p.w;
            }
            *(float4*)(rb + (size_t)i * D_ + dt * 4) = t;
        }
    }
}

// ---------------------------------------------------------------------------
extern "C" void kernel_launch(void* const* d_in, const int* in_sizes, int n_in,
                              void* d_out, int out_size)
{
    const float* H = (const float*)d_in[0];
    const float* w = (const float*)d_in[1];
    // d_in[2] = w_bias: softmax is shift-invariant and scores are not an
    // output, so the bias has no effect on (r, alpha) -> intentionally unused.

    float* out   = (float*)d_out;
    float* r     = out;                          // (B, L, D)
    float* alpha = out + (size_t)B_ * L_ * D_;   // (B, L, L); also scores scratch

    size_t smA = (size_t)(32 * D_ + D_ * 33 + D_ + 32 * 33) * sizeof(float);
    cudaFuncSetAttribute(scores_kernel, cudaFuncAttributeMaxDynamicSharedMemorySize, (int)smA);

    scores_kernel<<<dim3(136, B_), 256, smA>>>(H, w, alpha);
    softmax_r_kernel<<<dim3(64, B_), 256>>>(H, alpha, r);
}